// round 10
// baseline (speedup 1.0000x reference)
#include <cuda_runtime.h>
#include <math.h>

#define B_    32
#define N_    512
#define H_    8

typedef unsigned long long ull;

// ---------------- scratch (device globals; no allocation) ----------------
__device__ float g_x   [B_*N_*H_*64];     // 33.5 MB  post-attn layer1 (transposed)
__device__ float g_Wh2 [B_*N_*64];        // 4 MB
__device__ float g_s2s [B_*N_];
__device__ float g_s2d [B_*N_];
__device__ float g_z   [B_*N_*64];        // 4 MB (fc1 input)
__device__ float g_p1  [256*B_*256];      // 8 MB fc1 split-K partials
__device__ float g_z1  [B_*256];
__device__ float g_z2  [B_*256];

// ---------------- f32x2 packed-FMA helpers ----------------
__device__ __forceinline__ ull pk2(float x, float y) {
    ull r;
    asm("mov.b64 %0, {%1, %2};" : "=l"(r) : "r"(__float_as_uint(x)), "r"(__float_as_uint(y)));
    return r;
}
__device__ __forceinline__ float2 up2(ull v) {
    unsigned lo, hi;
    asm("mov.b64 {%0, %1}, %2;" : "=r"(lo), "=r"(hi) : "l"(v));
    return make_float2(__uint_as_float(lo), __uint_as_float(hi));
}
__device__ __forceinline__ void ffma2(ull& d, ull a, ull b) {
    asm("fma.rn.f32x2 %0, %1, %2, %0;" : "+l"(d) : "l"(a), "l"(b));
}

#define PITCH 68   // generic smem pitch (gemm2)
#define WHP   68   // Wh smem pitch
#define ASP   20   // A-chunk pitch
#define CPW   66   // prefix-table pitch (65 cols: 64 data + denominator)

// ============== shared attend phase (sorted-prefix factorized GAT) ========
__device__ __forceinline__ void attend_phase(
    float* __restrict__ Wh, float* sS, float* dS, float* ds,
    float* Ed, float* Ed2, int* ji, ull* skey, float* CP1, float* CP2,
    int* rowK, float* rowA, float* rowB, float* rowI,
    int tid, int r0, int r1, float* outBase, int rowStride, int applyElu)
{
    __syncthreads();
    // hybrid bitonic sort, descending (u64 keys: order-mapped d | idx)
    unsigned u0 = __float_as_uint(dS[tid]);
    u0 = (u0 & 0x80000000u) ? ~u0 : (u0 | 0x80000000u);
    ull v = ((ull)u0 << 32) | (unsigned)tid;
    for (int k2 = 2; k2 <= 512; k2 <<= 1) {
        for (int j = k2 >> 1; j; j >>= 1) {
            ull p;
            if (j >= 32) {
                __syncthreads();
                skey[tid] = v;
                __syncthreads();
                p = skey[tid ^ j];
            } else {
                p = __shfl_xor_sync(0xffffffffu, v, j);
            }
            bool keepBig = (((tid & j) == 0) == ((tid & k2) == 0));
            if (keepBig ? (p > v) : (p < v)) v = p;
        }
    }
    __syncthreads();
    int myj = (int)(unsigned)(v & 0xFFFFFFFFu);
    ji[tid] = myj;
    float dv_own = dS[myj];
    ds[tid] = dv_own;
    __syncthreads();
    float dmax = ds[0];
    float dd = dv_own - dmax;
    Ed[tid]  = expf(dd);
    Ed2[tid] = expf(0.2f*dd);
    __syncthreads();
    // chunk-8 sums; col 64 = denominator
    for (int idx = tid; idx < 64*65; idx += 512) {
        int c = idx / 65, o = idx - c*65;
        float s1 = 0.f, s2 = 0.f;
        #pragma unroll
        for (int uu = 0; uu < 8; uu++) {
            int su = c*8 + uu;
            float e1 = Ed[su], e2 = Ed2[su];
            float wv = (o < 64) ? Wh[ji[su]*WHP + o] : 1.0f;
            s1 += e1*wv; s2 += e2*wv;
        }
        CP1[(c+1)*CPW + o] = s1;
        CP2[(c+1)*CPW + o] = s2;
    }
    if (tid < CPW) { CP1[tid] = 0.f; CP2[tid] = 0.f; }
    __syncthreads();
    // Hillis-Steele inclusive scan over 64 chunk rows
    for (int off = 1; off <= 32; off <<= 1) {
        float t1[9], t2[9];
        int n = 0;
        for (int idx = tid; idx < 64*65; idx += 512, n++) {
            int pos = idx / 65 + 1, col = idx - (pos-1)*65;
            bool ok = pos > off;
            t1[n] = ok ? CP1[(pos-off)*CPW + col] : 0.f;
            t2[n] = ok ? CP2[(pos-off)*CPW + col] : 0.f;
        }
        __syncthreads();
        n = 0;
        for (int idx = tid; idx < 64*65; idx += 512, n++) {
            int pos = idx / 65 + 1, col = idx - (pos-1)*65;
            CP1[pos*CPW + col] += t1[n];
            CP2[pos*CPW + col] += t2[n];
        }
        __syncthreads();
    }
    // per-row precompute: thread = row (512 parallel searches, one pass)
    {
        float s   = sS[tid];
        float sd0 = s + dmax;
        float m   = fmaxf(sd0, 0.2f*sd0);
        float A   = expf(sd0 - m);
        float Bv  = expf(0.2f*sd0 - m);
        float thr = -s;
        int lo = 0, hi = 512;
        #pragma unroll
        for (int it = 0; it < 9; it++) {
            int mid = (lo + hi) >> 1;
            if (ds[mid] > thr) lo = mid + 1; else hi = mid;
        }
        int k = lo, c = k >> 3;
        float pe1 = 0.f, pe2 = 0.f;
        for (int u2 = c*8; u2 < k; u2++) { pe1 += Ed[u2]; pe2 += Ed2[u2]; }
        float d1 = CP1[c*CPW + 64] + pe1;
        float d2 = CP2[64*CPW + 64] - CP2[c*CPW + 64] - pe2;
        rowK[tid] = k;
        rowA[tid] = A;
        rowB[tid] = Bv;
        rowI[tid] = 1.f / (A*d1 + Bv*d2);
    }
    __syncthreads();
    // per-row column pass: prefix lookup + <=7-term correction
    int w = tid >> 5, l = tid & 31;
    float2 T2v = *(const float2*)(CP2 + 64*CPW + 2*l);
    for (int r = r0 + w; r < r1; r += 16) {
        int   k   = rowK[r];
        float A   = rowA[r];
        float Bv  = rowB[r];
        float inv = rowI[r];
        int c = k >> 3;
        float a1x=0.f, a1y=0.f, a2x=0.f, a2y=0.f;
        for (int u2 = c*8; u2 < k; u2++) {
            float e1 = Ed[u2], e2 = Ed2[u2];
            float2 wv = *(const float2*)(Wh + ji[u2]*WHP + 2*l);
            a1x += e1*wv.x; a1y += e1*wv.y;
            a2x += e2*wv.x; a2y += e2*wv.y;
        }
        float2 p1 = *(const float2*)(CP1 + c*CPW + 2*l);
        float2 p2 = *(const float2*)(CP2 + c*CPW + 2*l);
        float o0 = (A*(p1.x + a1x) + Bv*(T2v.x - p2.x - a2x))*inv;
        float o1 = (A*(p1.y + a1y) + Bv*(T2v.y - p2.y - a2y))*inv;
        if (applyElu) {
            o0 = o0 > 0.f ? o0 : expm1f(o0);
            o1 = o1 > 0.f ? o1 : expm1f(o1);
        }
        *(float2*)(outBase + (size_t)r*rowStride + 2*l) = make_float2(o0, o1);
    }
}

// ============== fused layer-1: GEMM(512x64x64) + scores + attend ==========
// grid 256 = (b,h); 512 threads.
__global__ __launch_bounds__(512) void k_fused1(
    const float* __restrict__ state, const float* __restrict__ Wheads,
    const float* __restrict__ a_src, const float* __restrict__ a_dst)
{
    extern __shared__ float sm[];
    float* Wh     = sm;                    // 512*68 = 34816
    float* Ws     = sm + 34816;            // 64*68  = 4352
    float* region = sm + 39168;            // 10240 (As | skey | CP1+CP2)
    float* As     = region;
    ull*   skey   = (ull*)region;
    float* CP1    = region;
    float* CP2    = region + 65*CPW;
    float* sS     = sm + 49408;
    float* dS     = sS + 512;
    float* ds     = dS + 512;
    float* Ed     = ds + 512;
    float* Ed2    = Ed + 512;
    int*   ji     = (int*)(Ed2 + 512);
    int*   rowK   = (int*)(sm + 52480);
    float* rowA   = sm + 52992;
    float* rowB   = sm + 53504;
    float* rowI   = sm + 54016;            // end 54528 floats

    int bid = blockIdx.x;
    int b = bid >> 3, h = bid & 7;
    int tid = threadIdx.x;
    int tx = tid & 7, ty = tid >> 3;

    {
        const float4* wp = (const float4*)(Wheads + h*64*64);
        #pragma unroll
        for (int i = 0; i < 2; i++) {
            int idx = tid + i*512;
            int r = idx >> 4, c4 = idx & 15;
            *(float4*)(Ws + r*WHP + c4*4) = wp[idx];
        }
    }
    ull acc[8][4] = {};
    const float4* sp = (const float4*)(state + (size_t)b*N_*64);
    for (int kc = 0; kc < 4; kc++) {
        __syncthreads();
        #pragma unroll
        for (int i = 0; i < 4; i++) {
            int idx = tid + i*512;
            int r = idx >> 2, q = idx & 3;
            *(float4*)(As + r*ASP + q*4) = sp[r*16 + kc*4 + q];
        }
        __syncthreads();
        #pragma unroll
        for (int k = 0; k < 16; k++) {
            ulonglong2 w0 = *(const ulonglong2*)(Ws + (kc*16+k)*WHP + tx*8);
            ulonglong2 w1 = *(const ulonglong2*)(Ws + (kc*16+k)*WHP + tx*8 + 4);
            #pragma unroll
            for (int i = 0; i < 8; i++) {
                float a = As[(ty + 64*i)*ASP + k];
                ull ap = pk2(a, a);
                ffma2(acc[i][0], ap, w0.x);
                ffma2(acc[i][1], ap, w0.y);
                ffma2(acc[i][2], ap, w1.x);
                ffma2(acc[i][3], ap, w1.y);
            }
        }
    }
    float as_[8], ad_[8];
    #pragma unroll
    for (int j2 = 0; j2 < 8; j2++) {
        as_[j2] = a_src[h*64 + tx*8 + j2];
        ad_[j2] = a_dst[h*64 + tx*8 + j2];
    }
    #pragma unroll
    for (int i = 0; i < 8; i++) {
        int r = ty + 64*i;
        *(ulonglong2*)(Wh + r*WHP + tx*8)     = make_ulonglong2(acc[i][0], acc[i][1]);
        *(ulonglong2*)(Wh + r*WHP + tx*8 + 4) = make_ulonglong2(acc[i][2], acc[i][3]);
        float ps = 0.f, pd = 0.f;
        #pragma unroll
        for (int p = 0; p < 4; p++) {
            float2 uu = up2(acc[i][p]);
            ps += uu.x*as_[2*p] + uu.y*as_[2*p+1];
            pd += uu.x*ad_[2*p] + uu.y*ad_[2*p+1];
        }
        #pragma unroll
        for (int o = 1; o < 8; o <<= 1) {
            ps += __shfl_xor_sync(0xffffffffu, ps, o);
            pd += __shfl_xor_sync(0xffffffffu, pd, o);
        }
        if (tx == 0) { sS[r] = ps; dS[r] = pd; }
    }
    attend_phase(Wh, sS, dS, ds, Ed, Ed2, ji, skey, CP1, CP2,
                 rowK, rowA, rowB, rowI, tid,
                 0, 512, g_x + (size_t)b*N_*512 + h*64, 512, 1);
}

// ============== K3: Wh2 = x @ W_out (16384x512 @ 512x64) + fused scores ===
// grid 128 rowtiles of 128; 128 threads; 8x8 per thread.
__global__ void k_gemm2(const float* __restrict__ Wout,
                        const float* __restrict__ a_out_src, const float* __restrict__ a_out_dst) {
    extern __shared__ float sm[];
    float* Xs = sm;                 // [128][PITCH]
    float* Ws = sm + 128*PITCH;     // [64][PITCH]
    int rt = blockIdx.x;
    int tid = threadIdx.x;
    int tx = tid & 7, ty = tid >> 3;
    const float4* xp = (const float4*)(g_x + (size_t)rt*128*512);

    ull acc[8][4] = {};
    for (int kc = 0; kc < 8; kc++) {
        __syncthreads();
        #pragma unroll
        for (int i = 0; i < 16; i++) {
            int idx = tid + i*128;
            int r = idx >> 4, k4 = idx & 15;
            *(float4*)(Xs + r*PITCH + 4*k4) = xp[r*128 + kc*16 + k4];
        }
        const float4* wp = (const float4*)(Wout + kc*64*64);
        #pragma unroll
        for (int i = 0; i < 8; i++) {
            int idx = tid + i*128;
            int k = idx >> 4, c4 = idx & 15;
            *(float4*)(Ws + k*PITCH + 4*c4) = wp[idx];
        }
        __syncthreads();
        #pragma unroll 8
        for (int k = 0; k < 64; k++) {
            ulonglong2 w0 = *(const ulonglong2*)(Ws + k*PITCH + tx*8);
            ulonglong2 w1 = *(const ulonglong2*)(Ws + k*PITCH + tx*8 + 4);
            #pragma unroll
            for (int i = 0; i < 8; i++) {
                float a = Xs[(ty + 16*i)*PITCH + k];
                ull ap = pk2(a, a);
                ffma2(acc[i][0], ap, w0.x);
                ffma2(acc[i][1], ap, w0.y);
                ffma2(acc[i][2], ap, w1.x);
                ffma2(acc[i][3], ap, w1.y);
            }
        }
    }
    int b  = (rt*128) >> 9;
    int n0 = (rt*128) & 511;
    float* op = g_Wh2 + (size_t)rt*128*64;
    float as_[8], ad_[8];
    #pragma unroll
    for (int j = 0; j < 8; j++) { as_[j] = a_out_src[tx*8 + j]; ad_[j] = a_out_dst[tx*8 + j]; }
    #pragma unroll
    for (int i = 0; i < 8; i++) {
        int r = ty + 16*i;
        ulonglong2 v0; v0.x = acc[i][0]; v0.y = acc[i][1];
        ulonglong2 v1; v1.x = acc[i][2]; v1.y = acc[i][3];
        *(ulonglong2*)(op + r*64 + tx*8)     = v0;
        *(ulonglong2*)(op + r*64 + tx*8 + 4) = v1;
        float ps = 0.f, pd = 0.f;
        #pragma unroll
        for (int p = 0; p < 4; p++) {
            float2 u = up2(acc[i][p]);
            ps += u.x*as_[2*p] + u.y*as_[2*p+1];
            pd += u.x*ad_[2*p] + u.y*ad_[2*p+1];
        }
        #pragma unroll
        for (int o = 1; o < 8; o <<= 1) {
            ps += __shfl_xor_sync(0xffffffffu, ps, o);
            pd += __shfl_xor_sync(0xffffffffu, pd, o);
        }
        if (tx == 0) {
            g_s2s[b*N_ + n0 + r] = ps;
            g_s2d[b*N_ + n0 + r] = pd;
        }
    }
}

// ============== K4: layer-2 attend, 4-way row split ==============
// grid 128 = (b, quarter); 512 threads.
__global__ __launch_bounds__(512) void k_attend2() {
    extern __shared__ float sm[];
    float* Wh     = sm;                    // 34816
    float* region = sm + 34816;            // 8580 (skey | CP1+CP2)
    ull*   skey   = (ull*)region;
    float* CP1    = region;
    float* CP2    = region + 65*CPW;
    float* sS     = sm + 43396;
    float* dS     = sS + 512;
    float* ds     = dS + 512;
    float* Ed     = ds + 512;
    float* Ed2    = Ed + 512;
    int*   ji     = (int*)(Ed2 + 512);
    int*   rowK   = (int*)(sm + 46468);
    float* rowA   = sm + 46980;
    float* rowB   = sm + 47492;
    float* rowI   = sm + 48004;            // end 48516 floats

    int bid = blockIdx.x;
    int b = bid >> 2, q = bid & 3;
    int tid = threadIdx.x;
    const float4* src = (const float4*)(g_Wh2 + (size_t)b*N_*64);
    #pragma unroll
    for (int i = 0; i < 16; i++) {
        int idx = tid + i*512;
        int r = idx >> 4, c4 = idx & 15;
        *(float4*)(Wh + r*WHP + c4*4) = src[idx];
    }
    sS[tid] = g_s2s[b*N_ + tid];
    dS[tid] = g_s2d[b*N_ + tid];
    attend_phase(Wh, sS, dS, ds, Ed, Ed2, ji, skey, CP1, CP2,
                 rowK, rowA, rowB, rowI, tid,
                 q*128, q*128 + 128, g_z + (size_t)b*N_*64, 64, 0);
}

// ============== fc1: 4-col x 4-batch-pair register tile, split-K ==========
// grid 256 ksplits (Kchunk=128); 256 threads = 64 col-quads x 4 bp-groups.
__global__ __launch_bounds__(256) void k_fc1(const float* __restrict__ w1) {
    __shared__ ull zP[16*128];   // [bp][kk] packed batch-pairs of z
    int ksp = blockIdx.x;
    int k0 = ksp*128;
    int tid = threadIdx.x;
    #pragma unroll
    for (int i = 0; i < 8; i++) {
        int idx = tid + i*256;       // 0..2047
        int bp = idx >> 7, kk = idx & 127;
        zP[idx] = pk2(g_z[(size_t)(2*bp)*32768 + k0 + kk],
                      g_z[(size_t)(2*bp+1)*32768 + k0 + kk]);
    }
    __syncthreads();
    int tx = tid & 63, tg = tid >> 6;    // col-quad, bp-group
    ull acc[4][4] = {};                  // [bp][col]
    const float* wp = w1 + (size_t)k0*256 + tx*4;
    #pragma unroll 4
    for (int kk = 0; kk < 128; kk++) {
        float4 w4 = *(const float4*)(wp + (size_t)kk*256);
        ull wp0 = pk2(w4.x, w4.x), wp1 = pk2(w4.y, w4.y);
        ull wp2 = pk2(w4.z, w4.z), wp3 = pk2(w4.w, w4.w);
        #pragma unroll
        for (int bp = 0; bp < 4; bp++) {
            ull zv = zP[(tg*4 + bp)*128 + kk];
            ffma2(acc[bp][0], zv, wp0);
            ffma2(acc[bp][1], zv, wp1);
            ffma2(acc[bp][2], zv, wp2);
            ffma2(acc[bp][3], zv, wp3);
        }
    }
    float* pp = g_p1 + (size_t)ksp*8192 + tx*4;
    #pragma unroll
    for (int bp = 0; bp < 4; bp++) {
        int bb = (tg*4 + bp)*2;
        float2 u0 = up2(acc[bp][0]), u1 = up2(acc[bp][1]);
        float2 u2 = up2(acc[bp][2]), u3 = up2(acc[bp][3]);
        *(float4*)(pp + (size_t)bb*256)     = make_float4(u0.x, u1.x, u2.x, u3.x);
        *(float4*)(pp + (size_t)(bb+1)*256) = make_float4(u0.y, u1.y, u2.y, u3.y);
    }
}

// ============== fc1 reduce: parallel 2-stage (256 blocks, 256 partials) ===
// grid 256 = (b, cgroup of 32); 256 threads = (8 kspGroups x 32 cols).
__global__ __launch_bounds__(256) void k_fc1red(const float* __restrict__ b1) {
    __shared__ float red[8][33];
    int blk = blockIdx.x;
    int b = blk >> 3, cg = blk & 7;
    int tid = threadIdx.x;
    int kg = tid >> 5, cc = tid & 31;
    int c = cg*32 + cc;
    float acc = 0.f;
    const float* pp = g_p1 + (size_t)b*256 + c;
    #pragma unroll 8
    for (int i = 0; i < 32; i++)
        acc += pp[(size_t)(kg*32 + i)*8192];
    red[kg][cc] = acc;
    __syncthreads();
    if (kg == 0) {
        float s = b1[c];
        #pragma unroll
        for (int g = 0; g < 8; g++) s += red[g][cc];
        g_z1[b*256 + c] = fmaxf(s, 0.f);
    }
}

// ============== fc2 + relu (parallel: grid 128 = b x 4 col-groups) ========
// 256 threads = 64 cols x 4 kgroups.
__global__ __launch_bounds__(256) void k_fc2(const float* __restrict__ w2,
                                             const float* __restrict__ b2) {
    __shared__ float z1s[256];
    __shared__ float red[4][64];
    int b = blockIdx.x >> 2, cg = blockIdx.x & 3;
    int tid = threadIdx.x;
    int cc = tid & 63, kg = tid >> 6;
    int c = cg*64 + cc;
    z1s[tid] = g_z1[b*256 + tid];
    __syncthreads();
    float acc = 0.f;
    #pragma unroll 8
    for (int k = kg*64; k < kg*64 + 64; k++) acc += z1s[k]*w2[k*256 + c];
    red[kg][cc] = acc;
    __syncthreads();
    if (kg == 0) {
        float s = b2[c] + red[0][cc] + red[1][cc] + red[2][cc] + red[3][cc];
        g_z2[b*256 + c] = fmaxf(s, 0.f);
    }
}

// ============== fc3 + tanh ==============
__global__ void k_fc3(const float* __restrict__ w3, const float* __restrict__ b3,
                      float* __restrict__ out) {
    __shared__ float z2s[256];
    int b = blockIdx.x, tid = threadIdx.x;
    z2s[tid] = g_z2[b*256 + tid];
    z2s[tid + 128] = g_z2[b*256 + tid + 128];
    __syncthreads();
    int c = tid >> 5, l = tid & 31;
    float acc = 0.f;
    #pragma unroll
    for (int k = l; k < 256; k += 32) acc += z2s[k]*w3[k*4 + c];
    #pragma unroll
    for (int o = 16; o; o >>= 1) acc += __shfl_xor_sync(0xffffffffu, acc, o);
    if (l == 0) out[b*4 + c] = tanhf(acc + b3[c]);
}

// ---------------- launch ----------------
extern "C" void kernel_launch(void* const* d_in, const int* in_sizes, int n_in,
                              void* d_out, int out_size) {
    const float* state     = (const float*)d_in[0];
    const float* Wheads    = (const float*)d_in[1];
    const float* a_src     = (const float*)d_in[2];
    const float* a_dst     = (const float*)d_in[3];
    const float* Wout      = (const float*)d_in[4];
    const float* a_out_src = (const float*)d_in[5];
    const float* a_out_dst = (const float*)d_in[6];
    const float* fc1_w     = (const float*)d_in[7];
    const float* fc1_b     = (const float*)d_in[8];
    const float* fc2_w     = (const float*)d_in[9];
    const float* fc2_b     = (const float*)d_in[10];
    const float* fc3_w     = (const float*)d_in[11];
    const float* fc3_b     = (const float*)d_in[12];
    float* out = (float*)d_out;

    const int fused1Smem  = 54528 * 4;                 // 218112 B
    const int attend2Smem = 48516 * 4;                 // 194064 B
    const int gemmSmem    = (128*PITCH + 64*PITCH)*4;  // 52224 B
    cudaFuncSetAttribute(k_fused1,  cudaFuncAttributeMaxDynamicSharedMemorySize, fused1Smem);
    cudaFuncSetAttribute(k_attend2, cudaFuncAttributeMaxDynamicSharedMemorySize, attend2Smem);
    cudaFuncSetAttribute(k_gemm2,   cudaFuncAttributeMaxDynamicSharedMemorySize, gemmSmem);

    // layer 1: fully fused per (b,h)
    k_fused1<<<256, 512, fused1Smem>>>(state, Wheads, a_src, a_dst);
    // layer 2
    k_gemm2<<<128, 128, gemmSmem>>>(Wout, a_out_src, a_out_dst);
    k_attend2<<<128, 512, attend2Smem>>>();
    // MLP head
    k_fc1<<<256, 256>>>(fc1_w);
    k_fc1red<<<256, 256>>>(fc1_b);
    k_fc2<<<128, 256>>>(fc2_w, fc2_b);
    k_fc3<<<B_, 128>>>(fc3_w, fc3_b, out);
}

// round 14
// speedup vs baseline: 1.2974x; 1.2974x over previous
#include <cuda_runtime.h>
#include <math.h>

#define B_    32
#define N_    512
#define H_    8

typedef unsigned long long ull;

// ---------------- scratch (device globals; no allocation) ----------------
__device__ float g_x   [B_*N_*H_*64];     // 33.5 MB  post-attn layer1 (transposed)
__device__ float g_Wh2 [B_*N_*64];        // 4 MB
__device__ float g_s2s [B_*N_];
__device__ float g_s2d [B_*N_];
__device__ float g_z   [B_*N_*64];        // 4 MB (fc1 input)
__device__ float g_p1  [256*B_*256];      // 8 MB fc1 split-K partials
__device__ float g_z1  [B_*256];
__device__ float g_z2  [B_*256];

// ---------------- f32x2 packed-FMA helpers ----------------
__device__ __forceinline__ ull pk2(float x, float y) {
    ull r;
    asm("mov.b64 %0, {%1, %2};" : "=l"(r) : "r"(__float_as_uint(x)), "r"(__float_as_uint(y)));
    return r;
}
__device__ __forceinline__ float2 up2(ull v) {
    unsigned lo, hi;
    asm("mov.b64 {%0, %1}, %2;" : "=r"(lo), "=r"(hi) : "l"(v));
    return make_float2(__uint_as_float(lo), __uint_as_float(hi));
}
__device__ __forceinline__ void ffma2(ull& d, ull a, ull b) {
    asm("fma.rn.f32x2 %0, %1, %2, %0;" : "+l"(d) : "l"(a), "l"(b));
}

#define PITCH 68   // generic smem pitch (gemm2)
#define WHP   68   // Wh smem pitch
#define ASP   20   // A-chunk pitch
#define CPW   66   // prefix-table pitch (65 cols: 64 data + denominator)

// ============== shared attend phase (sorted-prefix factorized GAT) ========
__device__ __forceinline__ void attend_phase(
    float* __restrict__ Wh, float* sS, float* dS, float* ds,
    float* Ed, float* Ed2, int* ji, ull* skey, float* CP1, float* CP2,
    int tid, int r0, int r1, float* outBase, int rowStride, int applyElu)
{
    __syncthreads();
    // hybrid bitonic sort, descending (u64 keys: order-mapped d | idx)
    unsigned u0 = __float_as_uint(dS[tid]);
    u0 = (u0 & 0x80000000u) ? ~u0 : (u0 | 0x80000000u);
    ull v = ((ull)u0 << 32) | (unsigned)tid;
    for (int k2 = 2; k2 <= 512; k2 <<= 1) {
        for (int j = k2 >> 1; j; j >>= 1) {
            ull p;
            if (j >= 32) {
                __syncthreads();
                skey[tid] = v;
                __syncthreads();
                p = skey[tid ^ j];
            } else {
                p = __shfl_xor_sync(0xffffffffu, v, j);
            }
            bool keepBig = (((tid & j) == 0) == ((tid & k2) == 0));
            if (keepBig ? (p > v) : (p < v)) v = p;
        }
    }
    __syncthreads();
    int myj = (int)(unsigned)(v & 0xFFFFFFFFu);
    ji[tid] = myj;
    float dv_own = dS[myj];
    ds[tid] = dv_own;
    __syncthreads();
    float dmax = ds[0];
    float dd = dv_own - dmax;
    Ed[tid]  = expf(dd);
    Ed2[tid] = expf(0.2f*dd);
    __syncthreads();
    // chunk-8 sums; col 64 = denominator
    for (int idx = tid; idx < 64*65; idx += 512) {
        int c = idx / 65, o = idx - c*65;
        float s1 = 0.f, s2 = 0.f;
        #pragma unroll
        for (int uu = 0; uu < 8; uu++) {
            int su = c*8 + uu;
            float e1 = Ed[su], e2 = Ed2[su];
            float wv = (o < 64) ? Wh[ji[su]*WHP + o] : 1.0f;
            s1 += e1*wv; s2 += e2*wv;
        }
        CP1[(c+1)*CPW + o] = s1;
        CP2[(c+1)*CPW + o] = s2;
    }
    if (tid < CPW) { CP1[tid] = 0.f; CP2[tid] = 0.f; }
    __syncthreads();
    // Hillis-Steele inclusive scan over 64 chunk rows
    for (int off = 1; off <= 32; off <<= 1) {
        float t1[9], t2[9];
        int n = 0;
        for (int idx = tid; idx < 64*65; idx += 512, n++) {
            int pos = idx / 65 + 1, col = idx - (pos-1)*65;
            bool ok = pos > off;
            t1[n] = ok ? CP1[(pos-off)*CPW + col] : 0.f;
            t2[n] = ok ? CP2[(pos-off)*CPW + col] : 0.f;
        }
        __syncthreads();
        n = 0;
        for (int idx = tid; idx < 64*65; idx += 512, n++) {
            int pos = idx / 65 + 1, col = idx - (pos-1)*65;
            CP1[pos*CPW + col] += t1[n];
            CP2[pos*CPW + col] += t2[n];
        }
        __syncthreads();
    }
    // per-row: binary search + prefix lookup + <=7-term correction
    int w = tid >> 5, l = tid & 31;
    float2 T2v  = *(const float2*)(CP2 + 64*CPW + 2*l);
    float  T2d  = CP2[64*CPW + 64];
    for (int r = r0 + w; r < r1; r += 16) {
        float s   = sS[r];
        float sd0 = s + dmax;
        float m   = fmaxf(sd0, 0.2f*sd0);
        float A   = expf(sd0 - m);
        float Bv  = expf(0.2f*sd0 - m);
        float thr = -s;
        int lo = 0, hi = 512;
        #pragma unroll
        for (int it = 0; it < 9; it++) {
            int mid = (lo + hi) >> 1;
            if (ds[mid] > thr) lo = mid + 1; else hi = mid;
        }
        int k = lo, c = k >> 3;
        float a1x=0.f, a1y=0.f, a2x=0.f, a2y=0.f, pe1=0.f, pe2=0.f;
        for (int u2 = c*8; u2 < k; u2++) {
            float e1 = Ed[u2], e2 = Ed2[u2];
            float2 wv = *(const float2*)(Wh + ji[u2]*WHP + 2*l);
            a1x += e1*wv.x; a1y += e1*wv.y;
            a2x += e2*wv.x; a2y += e2*wv.y;
            pe1 += e1;      pe2 += e2;
        }
        float2 p1 = *(const float2*)(CP1 + c*CPW + 2*l);
        float2 p2 = *(const float2*)(CP2 + c*CPW + 2*l);
        float d1 = CP1[c*CPW + 64] + pe1;
        float d2 = T2d - CP2[c*CPW + 64] - pe2;
        float inv = 1.f / (A*d1 + Bv*d2);
        float o0 = (A*(p1.x + a1x) + Bv*(T2v.x - p2.x - a2x))*inv;
        float o1 = (A*(p1.y + a1y) + Bv*(T2v.y - p2.y - a2y))*inv;
        if (applyElu) {
            o0 = o0 > 0.f ? o0 : expm1f(o0);
            o1 = o1 > 0.f ? o1 : expm1f(o1);
        }
        *(float2*)(outBase + (size_t)r*rowStride + 2*l) = make_float2(o0, o1);
    }
}

// ============== fused layer-1: GEMM(512x64x64) + scores + attend ==========
// grid 256 = (b,h); 512 threads.
__global__ __launch_bounds__(512) void k_fused1(
    const float* __restrict__ state, const float* __restrict__ Wheads,
    const float* __restrict__ a_src, const float* __restrict__ a_dst)
{
    extern __shared__ float sm[];
    float* Wh     = sm;                    // 512*68 = 34816
    float* Ws     = sm + 34816;            // 64*68  = 4352
    float* region = sm + 39168;            // 10240 (As | skey | CP1+CP2)
    float* As     = region;
    ull*   skey   = (ull*)region;
    float* CP1    = region;
    float* CP2    = region + 65*CPW;
    float* sS     = sm + 49408;
    float* dS     = sS + 512;
    float* ds     = dS + 512;
    float* Ed     = ds + 512;
    float* Ed2    = Ed + 512;
    int*   ji     = (int*)(Ed2 + 512);

    int bid = blockIdx.x;
    int b = bid >> 3, h = bid & 7;
    int tid = threadIdx.x;
    int tx = tid & 7, ty = tid >> 3;

    {
        const float4* wp = (const float4*)(Wheads + h*64*64);
        #pragma unroll
        for (int i = 0; i < 2; i++) {
            int idx = tid + i*512;
            int r = idx >> 4, c4 = idx & 15;
            *(float4*)(Ws + r*WHP + c4*4) = wp[idx];
        }
    }
    ull acc[8][4] = {};
    const float4* sp = (const float4*)(state + (size_t)b*N_*64);
    for (int kc = 0; kc < 4; kc++) {
        __syncthreads();
        #pragma unroll
        for (int i = 0; i < 4; i++) {
            int idx = tid + i*512;
            int r = idx >> 2, q = idx & 3;
            *(float4*)(As + r*ASP + q*4) = sp[r*16 + kc*4 + q];
        }
        __syncthreads();
        #pragma unroll
        for (int k = 0; k < 16; k++) {
            ulonglong2 w0 = *(const ulonglong2*)(Ws + (kc*16+k)*WHP + tx*8);
            ulonglong2 w1 = *(const ulonglong2*)(Ws + (kc*16+k)*WHP + tx*8 + 4);
            #pragma unroll
            for (int i = 0; i < 8; i++) {
                float a = As[(ty + 64*i)*ASP + k];
                ull ap = pk2(a, a);
                ffma2(acc[i][0], ap, w0.x);
                ffma2(acc[i][1], ap, w0.y);
                ffma2(acc[i][2], ap, w1.x);
                ffma2(acc[i][3], ap, w1.y);
            }
        }
    }
    float as_[8], ad_[8];
    #pragma unroll
    for (int j2 = 0; j2 < 8; j2++) {
        as_[j2] = a_src[h*64 + tx*8 + j2];
        ad_[j2] = a_dst[h*64 + tx*8 + j2];
    }
    #pragma unroll
    for (int i = 0; i < 8; i++) {
        int r = ty + 64*i;
        *(ulonglong2*)(Wh + r*WHP + tx*8)     = make_ulonglong2(acc[i][0], acc[i][1]);
        *(ulonglong2*)(Wh + r*WHP + tx*8 + 4) = make_ulonglong2(acc[i][2], acc[i][3]);
        float ps = 0.f, pd = 0.f;
        #pragma unroll
        for (int p = 0; p < 4; p++) {
            float2 uu = up2(acc[i][p]);
            ps += uu.x*as_[2*p] + uu.y*as_[2*p+1];
            pd += uu.x*ad_[2*p] + uu.y*ad_[2*p+1];
        }
        #pragma unroll
        for (int o = 1; o < 8; o <<= 1) {
            ps += __shfl_xor_sync(0xffffffffu, ps, o);
            pd += __shfl_xor_sync(0xffffffffu, pd, o);
        }
        if (tx == 0) { sS[r] = ps; dS[r] = pd; }
    }
    attend_phase(Wh, sS, dS, ds, Ed, Ed2, ji, skey, CP1, CP2, tid,
                 0, 512, g_x + (size_t)b*N_*512 + h*64, 512, 1);
}

// ============== K3: Wh2 = x @ W_out (16384x512 @ 512x64) + fused scores ===
// grid 128 rowtiles of 128; 128 threads; 8x8 per thread.
__global__ void k_gemm2(const float* __restrict__ Wout,
                        const float* __restrict__ a_out_src, const float* __restrict__ a_out_dst) {
    extern __shared__ float sm[];
    float* Xs = sm;                 // [128][PITCH]
    float* Ws = sm + 128*PITCH;     // [64][PITCH]
    int rt = blockIdx.x;
    int tid = threadIdx.x;
    int tx = tid & 7, ty = tid >> 3;
    const float4* xp = (const float4*)(g_x + (size_t)rt*128*512);

    ull acc[8][4] = {};
    for (int kc = 0; kc < 8; kc++) {
        __syncthreads();
        #pragma unroll
        for (int i = 0; i < 16; i++) {
            int idx = tid + i*128;
            int r = idx >> 4, k4 = idx & 15;
            *(float4*)(Xs + r*PITCH + 4*k4) = xp[r*128 + kc*16 + k4];
        }
        const float4* wp = (const float4*)(Wout + kc*64*64);
        #pragma unroll
        for (int i = 0; i < 8; i++) {
            int idx = tid + i*128;
            int k = idx >> 4, c4 = idx & 15;
            *(float4*)(Ws + k*PITCH + 4*c4) = wp[idx];
        }
        __syncthreads();
        #pragma unroll 8
        for (int k = 0; k < 64; k++) {
            ulonglong2 w0 = *(const ulonglong2*)(Ws + k*PITCH + tx*8);
            ulonglong2 w1 = *(const ulonglong2*)(Ws + k*PITCH + tx*8 + 4);
            #pragma unroll
            for (int i = 0; i < 8; i++) {
                float a = Xs[(ty + 16*i)*PITCH + k];
                ull ap = pk2(a, a);
                ffma2(acc[i][0], ap, w0.x);
                ffma2(acc[i][1], ap, w0.y);
                ffma2(acc[i][2], ap, w1.x);
                ffma2(acc[i][3], ap, w1.y);
            }
        }
    }
    int b  = (rt*128) >> 9;
    int n0 = (rt*128) & 511;
    float* op = g_Wh2 + (size_t)rt*128*64;
    float as_[8], ad_[8];
    #pragma unroll
    for (int j = 0; j < 8; j++) { as_[j] = a_out_src[tx*8 + j]; ad_[j] = a_out_dst[tx*8 + j]; }
    #pragma unroll
    for (int i = 0; i < 8; i++) {
        int r = ty + 16*i;
        ulonglong2 v0; v0.x = acc[i][0]; v0.y = acc[i][1];
        ulonglong2 v1; v1.x = acc[i][2]; v1.y = acc[i][3];
        *(ulonglong2*)(op + r*64 + tx*8)     = v0;
        *(ulonglong2*)(op + r*64 + tx*8 + 4) = v1;
        float ps = 0.f, pd = 0.f;
        #pragma unroll
        for (int p = 0; p < 4; p++) {
            float2 u = up2(acc[i][p]);
            ps += u.x*as_[2*p] + u.y*as_[2*p+1];
            pd += u.x*ad_[2*p] + u.y*ad_[2*p+1];
        }
        #pragma unroll
        for (int o = 1; o < 8; o <<= 1) {
            ps += __shfl_xor_sync(0xffffffffu, ps, o);
            pd += __shfl_xor_sync(0xffffffffu, pd, o);
        }
        if (tx == 0) {
            g_s2s[b*N_ + n0 + r] = ps;
            g_s2d[b*N_ + n0 + r] = pd;
        }
    }
}

// ============== K4: layer-2 attend, 4-way row split ==============
// grid 128 = (b, quarter); 512 threads.
__global__ __launch_bounds__(512) void k_attend2() {
    extern __shared__ float sm[];
    float* Wh     = sm;                    // 34816
    float* region = sm + 34816;            // 8580 (skey | CP1+CP2)
    ull*   skey   = (ull*)region;
    float* CP1    = region;
    float* CP2    = region + 65*CPW;
    float* sS     = sm + 43396;
    float* dS     = sS + 512;
    float* ds     = dS + 512;
    float* Ed     = ds + 512;
    float* Ed2    = Ed + 512;
    int*   ji     = (int*)(Ed2 + 512);

    int bid = blockIdx.x;
    int b = bid >> 2, q = bid & 3;
    int tid = threadIdx.x;
    const float4* src = (const float4*)(g_Wh2 + (size_t)b*N_*64);
    #pragma unroll
    for (int i = 0; i < 16; i++) {
        int idx = tid + i*512;
        int r = idx >> 4, c4 = idx & 15;
        *(float4*)(Wh + r*WHP + c4*4) = src[idx];
    }
    sS[tid] = g_s2s[b*N_ + tid];
    dS[tid] = g_s2d[b*N_ + tid];
    attend_phase(Wh, sS, dS, ds, Ed, Ed2, ji, skey, CP1, CP2, tid,
                 q*128, q*128 + 128, g_z + (size_t)b*N_*64, 64, 0);
}

// ============== fc1: deep-prefetch split-K (MLP=8) ==============
// grid 256 ksplits (Kchunk=128); 256 threads = 64 col-quads x 4 bp-groups.
__global__ __launch_bounds__(256) void k_fc1(const float* __restrict__ w1) {
    __shared__ ull zP[16*128];   // [bp][kk] packed batch-pairs of z
    int ksp = blockIdx.x;
    int k0 = ksp*128;
    int tid = threadIdx.x;
    #pragma unroll
    for (int i = 0; i < 8; i++) {
        int idx = tid + i*256;       // 0..2047
        int bp = idx >> 7, kk = idx & 127;
        zP[idx] = pk2(g_z[(size_t)(2*bp)*32768 + k0 + kk],
                      g_z[(size_t)(2*bp+1)*32768 + k0 + kk]);
    }
    __syncthreads();
    int tx = tid & 63, tg = tid >> 6;    // col-quad, bp-group
    ull acc[4][4] = {};                  // [bp][col]
    const float4* wp = (const float4*)(w1 + (size_t)k0*256 + tx*4);
    #pragma unroll
    for (int kb = 0; kb < 128; kb += 8) {
        // prefetch 8 weight rows (8 independent LDG.128 -> MLP 8)
        float4 wbuf[8];
        #pragma unroll
        for (int j = 0; j < 8; j++)
            wbuf[j] = wp[(size_t)(kb + j)*64];
        #pragma unroll
        for (int j = 0; j < 8; j++) {
            float4 w4 = wbuf[j];
            ull wp0 = pk2(w4.x, w4.x), wp1 = pk2(w4.y, w4.y);
            ull wp2 = pk2(w4.z, w4.z), wp3 = pk2(w4.w, w4.w);
            #pragma unroll
            for (int bp = 0; bp < 4; bp++) {
                ull zv = zP[(tg*4 + bp)*128 + kb + j];
                ffma2(acc[bp][0], zv, wp0);
                ffma2(acc[bp][1], zv, wp1);
                ffma2(acc[bp][2], zv, wp2);
                ffma2(acc[bp][3], zv, wp3);
            }
        }
    }
    float* pp = g_p1 + (size_t)ksp*8192 + tx*4;
    #pragma unroll
    for (int bp = 0; bp < 4; bp++) {
        int bb = (tg*4 + bp)*2;
        float2 u0 = up2(acc[bp][0]), u1 = up2(acc[bp][1]);
        float2 u2 = up2(acc[bp][2]), u3 = up2(acc[bp][3]);
        *(float4*)(pp + (size_t)bb*256)     = make_float4(u0.x, u1.x, u2.x, u3.x);
        *(float4*)(pp + (size_t)(bb+1)*256) = make_float4(u0.y, u1.y, u2.y, u3.y);
    }
}

// ============== fc1 reduce: parallel 2-stage (256 blocks, 256 partials) ===
// grid 256 = (b, cgroup of 32); 256 threads = (8 kspGroups x 32 cols).
__global__ __launch_bounds__(256) void k_fc1red(const float* __restrict__ b1) {
    __shared__ float red[8][33];
    int blk = blockIdx.x;
    int b = blk >> 3, cg = blk & 7;
    int tid = threadIdx.x;
    int kg = tid >> 5, cc = tid & 31;
    int c = cg*32 + cc;
    float acc = 0.f;
    const float* pp = g_p1 + (size_t)b*256 + c;
    #pragma unroll 8
    for (int i = 0; i < 32; i++)
        acc += pp[(size_t)(kg*32 + i)*8192];
    red[kg][cc] = acc;
    __syncthreads();
    if (kg == 0) {
        float s = b1[c];
        #pragma unroll
        for (int g = 0; g < 8; g++) s += red[g][cc];
        g_z1[b*256 + c] = fmaxf(s, 0.f);
    }
}

// ============== fc2 + relu ==============
__global__ void k_fc2(const float* __restrict__ w2, const float* __restrict__ b2) {
    __shared__ float z1s[256];
    int b = blockIdx.x, c = threadIdx.x;
    z1s[c] = g_z1[b*256 + c];
    __syncthreads();
    float acc = b2[c];
    #pragma unroll 8
    for (int k = 0; k < 256; k++) acc += z1s[k]*w2[k*256 + c];
    g_z2[b*256 + c] = fmaxf(acc, 0.f);
}

// ============== fc3 + tanh ==============
__global__ void k_fc3(const float* __restrict__ w3, const float* __restrict__ b3,
                      float* __restrict__ out) {
    __shared__ float z2s[256];
    int b = blockIdx.x, tid = threadIdx.x;
    z2s[tid] = g_z2[b*256 + tid];
    z2s[tid + 128] = g_z2[b*256 + tid + 128];
    __syncthreads();
    int c = tid >> 5, l = tid & 31;
    float acc = 0.f;
    #pragma unroll
    for (int k = l; k < 256; k += 32) acc += z2s[k]*w3[k*4 + c];
    #pragma unroll
    for (int o = 16; o; o >>= 1) acc += __shfl_xor_sync(0xffffffffu, acc, o);
    if (l == 0) out[b*4 + c] = tanhf(acc + b3[c]);
}

// ---------------- launch ----------------
extern "C" void kernel_launch(void* const* d_in, const int* in_sizes, int n_in,
                              void* d_out, int out_size) {
    const float* state     = (const float*)d_in[0];
    const float* Wheads    = (const float*)d_in[1];
    const float* a_src     = (const float*)d_in[2];
    const float* a_dst     = (const float*)d_in[3];
    const float* Wout      = (const float*)d_in[4];
    const float* a_out_src = (const float*)d_in[5];
    const float* a_out_dst = (const float*)d_in[6];
    const float* fc1_w     = (const float*)d_in[7];
    const float* fc1_b     = (const float*)d_in[8];
    const float* fc2_w     = (const float*)d_in[9];
    const float* fc2_b     = (const float*)d_in[10];
    const float* fc3_w     = (const float*)d_in[11];
    const float* fc3_b     = (const float*)d_in[12];
    float* out = (float*)d_out;

    const int fused1Smem  = 52480 * 4;                 // 209920 B
    const int attend2Smem = 46468 * 4;                 // 185872 B
    const int gemmSmem    = (128*PITCH + 64*PITCH)*4;  // 52224 B
    cudaFuncSetAttribute(k_fused1,  cudaFuncAttributeMaxDynamicSharedMemorySize, fused1Smem);
    cudaFuncSetAttribute(k_attend2, cudaFuncAttributeMaxDynamicSharedMemorySize, attend2Smem);
    cudaFuncSetAttribute(k_gemm2,   cudaFuncAttributeMaxDynamicSharedMemorySize, gemmSmem);

    // layer 1: fully fused per (b,h)
    k_fused1<<<256, 512, fused1Smem>>>(state, Wheads, a_src, a_dst);
    // layer 2
    k_gemm2<<<128, 128, gemmSmem>>>(Wout, a_out_src, a_out_dst);
    k_attend2<<<128, 512, attend2Smem>>>();
    // MLP head
    k_fc1<<<256, 256>>>(fc1_w);
    k_fc1red<<<256, 256>>>(fc1_b);
    k_fc2<<<B_, 256>>>(fc2_w, fc2_b);
    k_fc3<<<B_, 128>>>(fc3_w, fc3_b, out);
}